// round 15
// baseline (speedup 1.0000x reference)
#include <cuda_runtime.h>
#include <cuda_fp16.h>
#include <math.h>
#include <stdint.h>

static constexpr int SEQ    = 2048;
static constexpr int HIDDEN = 2048;
static constexpr int NHEAD  = 16;
static constexpr int NKV    = 2;
static constexpr int HD     = 256;
static constexpr int QROW   = NHEAD * HD * 2;   // 8192
static constexpr int KROW   = NKV * HD;         // 512
static constexpr int ODIM   = NHEAD * HD;       // 4096
static constexpr float ATTN_SCALE_L2E = 0.0625f * 1.4426950408889634f;
static constexpr float MASKV = -1e30f;

// ---- scratch (static device memory; no allocations allowed) ----
__device__ __half g_hs_h  [(size_t)SEQ * HIDDEN];
__device__ __half g_wq_h  [(size_t)QROW * HIDDEN];
__device__ __half g_wk_h  [(size_t)KROW * HIDDEN];
__device__ __half g_wv_h  [(size_t)KROW * HIDDEN];
__device__ __half g_wo_h  [(size_t)HIDDEN * ODIM];
__device__ __half g_qout_h[(size_t)SEQ * QROW];
__device__ __half g_kbuf_h[(size_t)SEQ * KROW];
__device__ __half g_vt_h  [(size_t)KROW * SEQ];
__device__ __half g_obuf_h[(size_t)SEQ * ODIM];

// ============================ asm helpers ==================================
__device__ __forceinline__ uint32_t smem_u32(const void* p) {
    uint32_t a;
    asm("{ .reg .u64 t; cvta.to.shared.u64 t, %1; cvt.u32.u64 %0, t; }" : "=r"(a) : "l"(p));
    return a;
}
#define CP_ASYNC16(dst, src) \
    asm volatile("cp.async.cg.shared.global [%0], [%1], 16;" :: "r"(dst), "l"(src))
#define CP_COMMIT() asm volatile("cp.async.commit_group;")
#define CP_WAIT(n)  asm volatile("cp.async.wait_group %0;" :: "n"(n))

__device__ __forceinline__ void ldm_x4(uint32_t* r, uint32_t addr) {
    asm volatile("ldmatrix.sync.aligned.m8n8.x4.shared.b16 {%0,%1,%2,%3}, [%4];"
                 : "=r"(r[0]), "=r"(r[1]), "=r"(r[2]), "=r"(r[3]) : "r"(addr));
}
__device__ __forceinline__ void mma_f16(float* c, const uint32_t* a, const uint32_t* b) {
    asm volatile(
        "mma.sync.aligned.m16n8k16.row.col.f32.f16.f16.f32 "
        "{%0,%1,%2,%3}, {%4,%5,%6,%7}, {%8,%9}, {%0,%1,%2,%3};"
        : "+f"(c[0]), "+f"(c[1]), "+f"(c[2]), "+f"(c[3])
        : "r"(a[0]), "r"(a[1]), "r"(a[2]), "r"(a[3]), "r"(b[0]), "r"(b[1]));
}
__device__ __forceinline__ uint32_t h2u(__half2 v) {
    return *reinterpret_cast<uint32_t*>(&v);
}

// =============== fp16 NT GEMM, 128x128 tile (O-projection) =================
static constexpr int PIPE_S = 4;
static constexpr int STAGE_BYTES = 16384;
static constexpr int SMEM_BYTES  = PIPE_S * STAGE_BYTES;   // 64 KB

template<bool HALF_OUT>
__device__ __forceinline__ void hgemm_body(
    const __half* __restrict__ A, const __half* __restrict__ B, void* __restrict__ Cv,
    int m0, int n0, int K, int lda, int ldb, int ldc)
{
    int nk = K >> 5;
    extern __shared__ char smem[];
    uint32_t sb = smem_u32(smem);
    int tid = threadIdx.x, lane = tid & 31, wid = tid >> 5;
    int wm = wid >> 1, wn = wid & 1;
    int grp = lane >> 3, l7 = lane & 7;

    auto fill = [&](int st, int kt) {
        int k0 = kt << 5;
        uint32_t base = sb + st * STAGE_BYTES;
        #pragma unroll
        for (int i = 0; i < 2; i++) {
            int id = tid + i * 256, r = id >> 2, c = id & 3;
            CP_ASYNC16(base + r * 64 + ((c ^ ((r >> 1) & 3)) << 4),
                       A + (long long)(m0 + r) * lda + k0 + c * 8);
        }
        #pragma unroll
        for (int i = 0; i < 2; i++) {
            int id = tid + i * 256, r = id >> 2, c = id & 3;
            CP_ASYNC16(base + 8192 + r * 64 + ((c ^ ((r >> 1) & 3)) << 4),
                       B + (long long)(n0 + r) * ldb + k0 + c * 8);
        }
    };

    float acc[2][8][4] = {};

    #pragma unroll
    for (int st = 0; st < PIPE_S - 1; st++) {
        if (st < nk) fill(st, st);
        CP_COMMIT();
    }

    for (int kt = 0; kt < nk; kt++) {
        CP_WAIT(PIPE_S - 2);
        __syncthreads();
        if (kt + PIPE_S - 1 < nk) fill((kt + PIPE_S - 1) & 3, kt + PIPE_S - 1);
        CP_COMMIT();

        uint32_t abase = sb + (kt & 3) * STAGE_BYTES;
        uint32_t bbase = abase + 8192;
        #pragma unroll
        for (int s = 0; s < 2; s++) {
            uint32_t af[2][4], bf[4][4];
            #pragma unroll
            for (int mt = 0; mt < 2; mt++) {
                int row = wm * 32 + mt * 16 + l7 + ((grp & 1) << 3);
                int ch  = s * 2 + (grp >> 1);
                ldm_x4(af[mt], abase + row * 64 + ((ch ^ ((row >> 1) & 3)) << 4));
            }
            #pragma unroll
            for (int nt = 0; nt < 4; nt++) {
                int row = wn * 64 + nt * 16 + l7 + ((grp >> 1) << 3);
                int ch  = s * 2 + (grp & 1);
                ldm_x4(bf[nt], bbase + row * 64 + ((ch ^ ((row >> 1) & 3)) << 4));
            }
            #pragma unroll
            for (int mt = 0; mt < 2; mt++)
                #pragma unroll
                for (int nt = 0; nt < 4; nt++) {
                    mma_f16(acc[mt][nt * 2],     af[mt], &bf[nt][0]);
                    mma_f16(acc[mt][nt * 2 + 1], af[mt], &bf[nt][2]);
                }
        }
    }

    int g8 = lane >> 2, t2 = (lane & 3) * 2;
    #pragma unroll
    for (int mt = 0; mt < 2; mt++) {
        #pragma unroll
        for (int nt = 0; nt < 8; nt++) {
            long long row = m0 + wm * 32 + mt * 16 + g8;
            int col = n0 + wn * 64 + nt * 8 + t2;
            if (HALF_OUT) {
                __half* C = (__half*)Cv;
                *(__half2*)(C + row * ldc + col) =
                    __floats2half2_rn(acc[mt][nt][0], acc[mt][nt][1]);
                *(__half2*)(C + (row + 8) * ldc + col) =
                    __floats2half2_rn(acc[mt][nt][2], acc[mt][nt][3]);
            } else {
                float* C = (float*)Cv;
                *(float2*)(C + row * ldc + col) =
                    make_float2(acc[mt][nt][0], acc[mt][nt][1]);
                *(float2*)(C + (row + 8) * ldc + col) =
                    make_float2(acc[mt][nt][2], acc[mt][nt][3]);
            }
        }
    }
}

template<bool HALF_OUT>
__global__ __launch_bounds__(256, 2) void hgemm_nt(
    const __half* __restrict__ A, const __half* __restrict__ B, void* __restrict__ Cv,
    int K, int lda, int ldb, int ldc)
{
    hgemm_body<HALF_OUT>(A, B, Cv, blockIdx.y * 128, blockIdx.x * 128, K, lda, ldb, ldc);
}

// ========= fp16 NT GEMM, 128x256 tile, 64x64 warp tiles (QKV) ==============
// 8 warps as 2(m) x 4(n); per warp 64x64 -> 8 LDSM.x4 per 32 MMAs (ratio 4.0
// vs 2.67 for the 32x64 tile). acc=128 regs -> 1 CTA/SM.
static constexpr int STG2_A = 8192;                 // A 128x64B
static constexpr int STG2_BYTES = 8192 + 16384;     // + B 256x64B = 24576
static constexpr int SMEM2_BYTES = PIPE_S * STG2_BYTES;  // 98304

__device__ __forceinline__ void hgemm_body256(
    const __half* __restrict__ A, const __half* __restrict__ B, __half* __restrict__ C,
    int m0, int n0, int K, int lda, int ldb, int ldc)
{
    int nk = K >> 5;
    extern __shared__ char smem[];
    uint32_t sb = smem_u32(smem);
    int tid = threadIdx.x, lane = tid & 31, wid = tid >> 5;
    int wm = wid >> 2, wn = wid & 3;
    int grp = lane >> 3, l7 = lane & 7;

    auto fill = [&](int st, int kt) {
        int k0 = kt << 5;
        uint32_t base = sb + st * STG2_BYTES;
        #pragma unroll
        for (int i = 0; i < 2; i++) {
            int id = tid + i * 256, r = id >> 2, c = id & 3;
            CP_ASYNC16(base + r * 64 + ((c ^ ((r >> 1) & 3)) << 4),
                       A + (long long)(m0 + r) * lda + k0 + c * 8);
        }
        #pragma unroll
        for (int i = 0; i < 4; i++) {
            int id = tid + i * 256, r = id >> 2, c = id & 3;
            CP_ASYNC16(base + STG2_A + r * 64 + ((c ^ ((r >> 1) & 3)) << 4),
                       B + (long long)(n0 + r) * ldb + k0 + c * 8);
        }
    };

    float acc[4][8][4] = {};

    #pragma unroll
    for (int st = 0; st < PIPE_S - 1; st++) {
        if (st < nk) fill(st, st);
        CP_COMMIT();
    }

    for (int kt = 0; kt < nk; kt++) {
        CP_WAIT(PIPE_S - 2);
        __syncthreads();
        if (kt + PIPE_S - 1 < nk) fill((kt + PIPE_S - 1) & 3, kt + PIPE_S - 1);
        CP_COMMIT();

        uint32_t abase = sb + (kt & 3) * STG2_BYTES;
        uint32_t bbase = abase + STG2_A;
        #pragma unroll
        for (int s = 0; s < 2; s++) {
            uint32_t af[4][4], bf[4][4];
            #pragma unroll
            for (int mt = 0; mt < 4; mt++) {
                int row = wm * 64 + mt * 16 + l7 + ((grp & 1) << 3);
                int ch  = s * 2 + (grp >> 1);
                ldm_x4(af[mt], abase + row * 64 + ((ch ^ ((row >> 1) & 3)) << 4));
            }
            #pragma unroll
            for (int nb = 0; nb < 4; nb++) {
                int row = wn * 64 + nb * 16 + l7 + ((grp >> 1) << 3);
                int ch  = s * 2 + (grp & 1);
                ldm_x4(bf[nb], bbase + row * 64 + ((ch ^ ((row >> 1) & 3)) << 4));
            }
            #pragma unroll
            for (int mt = 0; mt < 4; mt++)
                #pragma unroll
                for (int nb = 0; nb < 4; nb++) {
                    mma_f16(acc[mt][nb * 2],     af[mt], &bf[nb][0]);
                    mma_f16(acc[mt][nb * 2 + 1], af[mt], &bf[nb][2]);
                }
        }
    }

    int g8 = lane >> 2, t2 = (lane & 3) * 2;
    #pragma unroll
    for (int mt = 0; mt < 4; mt++) {
        #pragma unroll
        for (int nt = 0; nt < 8; nt++) {
            long long row = m0 + wm * 64 + mt * 16 + g8;
            int col = n0 + wn * 64 + nt * 8 + t2;
            *(__half2*)(C + row * ldc + col) =
                __floats2half2_rn(acc[mt][nt][0], acc[mt][nt][1]);
            *(__half2*)(C + (row + 8) * ldc + col) =
                __floats2half2_rn(acc[mt][nt][2], acc[mt][nt][3]);
        }
    }
}

// Combined Q + K + V^T projections, 128x256 tiles (576 CTAs).
__global__ __launch_bounds__(256, 1) void hgemm_qkv(
    const __half* __restrict__ hs,  const __half* __restrict__ wq,
    const __half* __restrict__ wk,  const __half* __restrict__ wv,
    __half* __restrict__ qout, __half* __restrict__ kout, __half* __restrict__ vtout)
{
    int b = blockIdx.x;
    if (b < 512) {             // qout = hs @ wq^T   [2048 x 8192]
        hgemm_body256(hs, wq, qout, (b >> 5) << 7, (b & 31) << 8,
                      HIDDEN, HIDDEN, HIDDEN, QROW);
    } else if (b < 544) {      // kout = hs @ wk^T   [2048 x 512]
        int c = b - 512;
        hgemm_body256(hs, wk, kout, (c >> 1) << 7, (c & 1) << 8,
                      HIDDEN, HIDDEN, HIDDEN, KROW);
    } else {                   // vtout = wv @ hs^T  [512 x 2048]
        int c = b - 544;
        hgemm_body256(wv, hs, vtout, (c >> 3) << 7, (c & 7) << 8,
                      HIDDEN, HIDDEN, HIDDEN, SEQ);
    }
}

// ======================= fused flash attention =============================
// R14 body (best measured): 8 warps, warp = 16q x 256d, Q pre-scaled,
// log2-domain online softmax, kc-outer PV, exact rescale skip.
static constexpr int FQ_BYTES = 128 * 512;
static constexpr int FK_BYTES = 64 * 512;
static constexpr int FSTAGE   = FK_BYTES + 256 * 128;      // 65536
static constexpr int FSMEM    = FQ_BYTES + 2 * FSTAGE;     // 196608

__global__ __launch_bounds__(256, 1) void flash_attn(
    const __half* __restrict__ Qh, const __half* __restrict__ Kh,
    const __half* __restrict__ Vth, __half* __restrict__ O)
{
    int bx = blockIdx.x;
    int qt = 15 - (bx >> 4);          // heavy q-tiles first
    int h  = bx & 15;
    int q0 = qt << 7;
    int kv = h >> 3;
    int niter = (qt + 1) << 1;

    extern __shared__ char smem[];
    uint32_t sq = smem_u32(smem);

    int tid = threadIdx.x, lane = tid & 31, wid = tid >> 5;
    int grp = lane >> 3, l7 = lane & 7;
    int g8 = lane >> 2, t2 = (lane & 3) << 1;

    #pragma unroll
    for (int i = 0; i < 16; i++) {
        int id = tid + (i << 8);
        int r = id >> 5, c = id & 31;
        CP_ASYNC16(sq + r * 512 + ((c ^ (r & 7)) << 4),
                   Qh + (size_t)(q0 + r) * QROW + h * 512 + c * 8);
    }
    auto fillKV = [&](int it, int st) {
        int k0 = it << 6;
        uint32_t kb = sq + FQ_BYTES + st * FSTAGE;
        uint32_t vb = kb + FK_BYTES;
        #pragma unroll
        for (int i = 0; i < 8; i++) {
            int id = tid + (i << 8);
            int r = id >> 5, c = id & 31;
            CP_ASYNC16(kb + r * 512 + ((c ^ (r & 7)) << 4),
                       Kh + (size_t)(k0 + r) * KROW + kv * 256 + c * 8);
        }
        #pragma unroll
        for (int i = 0; i < 8; i++) {
            int id = tid + (i << 8);
            int d = id >> 3, c = id & 7;
            CP_ASYNC16(vb + d * 128 + ((c ^ (d & 7)) << 4),
                       Vth + (size_t)(kv * 256 + d) * SEQ + k0 + c * 8);
        }
    };
    fillKV(0, 0);
    CP_COMMIT();
    if (niter > 1) { fillKV(1, 1); CP_COMMIT(); }

    float m0 = MASKV, m1 = MASKV, l0 = 0.f, l1 = 0.f;   // log2 domain
    float accO[32][4] = {};
    int qrow0 = q0 + wid * 16 + g8;

    for (int it = 0; it < niter; it++) {
        int k0 = it << 6;
        if (it + 1 < niter) { CP_WAIT(1); } else { CP_WAIT(0); }
        __syncthreads();

        uint32_t kb = sq + FQ_BYTES + (it & 1) * FSTAGE;
        uint32_t vb = kb + FK_BYTES;

        // ---- S = Q K^T (Q pre-scaled) ----
        float accS[8][4] = {};
        #pragma unroll
        for (int s = 0; s < 16; s++) {
            uint32_t af[4];
            int qr = wid * 16 + l7 + ((grp & 1) << 3);
            int ch = s * 2 + (grp >> 1);
            ldm_x4(af, sq + qr * 512 + ((ch ^ (qr & 7)) << 4));
            #pragma unroll
            for (int np = 0; np < 4; np++) {
                uint32_t bf[4];
                int kr = np * 16 + l7 + ((grp >> 1) << 3);
                int c2 = s * 2 + (grp & 1);
                ldm_x4(bf, kb + kr * 512 + ((c2 ^ (kr & 7)) << 4));
                mma_f16(accS[np * 2],     af, &bf[0]);
                mma_f16(accS[np * 2 + 1], af, &bf[2]);
            }
        }

        if (k0 + 63 > q0 + wid * 16) {       // causal mask (diagonal tiles)
            #pragma unroll
            for (int nt = 0; nt < 8; nt++) {
                int c0 = k0 + nt * 8 + t2;
                if (c0 > qrow0)         accS[nt][0] = MASKV;
                if (c0 + 1 > qrow0)     accS[nt][1] = MASKV;
                if (c0 > qrow0 + 8)     accS[nt][2] = MASKV;
                if (c0 + 1 > qrow0 + 8) accS[nt][3] = MASKV;
            }
        }

        // ---- online softmax (log2 domain) ----
        float mx0 = MASKV, mx1 = MASKV;
        #pragma unroll
        for (int nt = 0; nt < 8; nt++) {
            mx0 = fmaxf(mx0, fmaxf(accS[nt][0], accS[nt][1]));
            mx1 = fmaxf(mx1, fmaxf(accS[nt][2], accS[nt][3]));
        }
        mx0 = fmaxf(mx0, __shfl_xor_sync(0xffffffffu, mx0, 1));
        mx0 = fmaxf(mx0, __shfl_xor_sync(0xffffffffu, mx0, 2));
        mx1 = fmaxf(mx1, __shfl_xor_sync(0xffffffffu, mx1, 1));
        mx1 = fmaxf(mx1, __shfl_xor_sync(0xffffffffu, mx1, 2));

        float mn0 = fmaxf(m0, mx0), mn1 = fmaxf(m1, mx1);
        int need = __any_sync(0xffffffffu, (mn0 != m0) || (mn1 != m1));
        float a0 = exp2f(m0 - mn0), a1 = exp2f(m1 - mn1);
        m0 = mn0; m1 = mn1;
        float s0 = 0.f, s1 = 0.f;
        #pragma unroll
        for (int nt = 0; nt < 8; nt++) {
            accS[nt][0] = exp2f(accS[nt][0] - mn0); s0 += accS[nt][0];
            accS[nt][1] = exp2f(accS[nt][1] - mn0); s0 += accS[nt][1];
            accS[nt][2] = exp2f(accS[nt][2] - mn1); s1 += accS[nt][2];
            accS[nt][3] = exp2f(accS[nt][3] - mn1); s1 += accS[nt][3];
        }
        s0 += __shfl_xor_sync(0xffffffffu, s0, 1);
        s0 += __shfl_xor_sync(0xffffffffu, s0, 2);
        s1 += __shfl_xor_sync(0xffffffffu, s1, 1);
        s1 += __shfl_xor_sync(0xffffffffu, s1, 2);
        l0 = l0 * a0 + s0;
        l1 = l1 * a1 + s1;
        if (need) {   // exact skip: a == 1 when no row max changed
            #pragma unroll
            for (int nt = 0; nt < 32; nt++) {
                accO[nt][0] *= a0; accO[nt][1] *= a0;
                accO[nt][2] *= a1; accO[nt][3] *= a1;
            }
        }

        // ---- P fragments (S accum layout == A operand layout) ----
        uint32_t pf[4][4];
        #pragma unroll
        for (int kc = 0; kc < 4; kc++) {
            pf[kc][0] = h2u(__floats2half2_rn(accS[2 * kc][0],     accS[2 * kc][1]));
            pf[kc][1] = h2u(__floats2half2_rn(accS[2 * kc][2],     accS[2 * kc][3]));
            pf[kc][2] = h2u(__floats2half2_rn(accS[2 * kc + 1][0], accS[2 * kc + 1][1]));
            pf[kc][3] = h2u(__floats2half2_rn(accS[2 * kc + 1][2], accS[2 * kc + 1][3]));
        }

        // ---- O += P V (kc outer) ----
        #pragma unroll
        for (int kc = 0; kc < 4; kc++) {
            #pragma unroll
            for (int np = 0; np < 16; np++) {
                uint32_t bf[4];
                int dr = np * 16 + l7 + ((grp >> 1) << 3);
                int ch = kc * 2 + (grp & 1);
                ldm_x4(bf, vb + dr * 128 + ((ch ^ (dr & 7)) << 4));
                mma_f16(accO[np * 2],     pf[kc], &bf[0]);
                mma_f16(accO[np * 2 + 1], pf[kc], &bf[2]);
            }
        }

        __syncthreads();
        if (it + 2 < niter) { fillKV(it + 2, it & 1); CP_COMMIT(); }
    }

    // ---- epilogue: 1/l, sigmoid gate, fp16 store ----
    float r0 = 1.f / l0, r1 = 1.f / l1;
    int trow0 = qrow0, trow1 = qrow0 + 8;
    const __half* G0 = Qh + (size_t)trow0 * QROW + h * 512 + 256;
    const __half* G1 = Qh + (size_t)trow1 * QROW + h * 512 + 256;
    __half* O0 = O + (size_t)trow0 * ODIM + h * 256;
    __half* O1 = O + (size_t)trow1 * ODIM + h * 256;
    #pragma unroll
    for (int nt = 0; nt < 32; nt++) {
        int d = nt * 8 + t2;
        float2 ga = __half22float2(*(const __half2*)(G0 + d));
        float2 gb = __half22float2(*(const __half2*)(G1 + d));
        float vx = accO[nt][0] * r0 / (1.f + __expf(-ga.x));
        float vy = accO[nt][1] * r0 / (1.f + __expf(-ga.y));
        float wx = accO[nt][2] * r1 / (1.f + __expf(-gb.x));
        float wy = accO[nt][3] * r1 / (1.f + __expf(-gb.y));
        *(__half2*)(O0 + d) = __floats2half2_rn(vx, vy);
        *(__half2*)(O1 + d) = __floats2half2_rn(wx, wy);
    }
}

// ============================ elementwise kernels ==========================
static constexpr long long F2H_N0 = (long long)SEQ * HIDDEN;
static constexpr long long F2H_N1 = (long long)QROW * HIDDEN;
static constexpr long long F2H_N2 = (long long)KROW * HIDDEN;
static constexpr long long F2H_N3 = (long long)KROW * HIDDEN;
static constexpr long long F2H_N4 = (long long)HIDDEN * ODIM;
static constexpr long long F2H_TOT = F2H_N0 + F2H_N1 + F2H_N2 + F2H_N3 + F2H_N4;

// 8 elements per thread: 2x LDG.128 -> 1x STG.128.
__global__ __launch_bounds__(256) void f2h_all(
    const float* __restrict__ s0, __half* __restrict__ d0,
    const float* __restrict__ s1, __half* __restrict__ d1,
    const float* __restrict__ s2, __half* __restrict__ d2,
    const float* __restrict__ s3, __half* __restrict__ d3,
    const float* __restrict__ s4, __half* __restrict__ d4)
{
    long long i = ((long long)blockIdx.x * 256 + threadIdx.x) * 8;
    if (i >= F2H_TOT) return;
    const float* s;
    __half* d;
    if (i < F2H_N0)                    { s = s0; d = d0; }
    else if ((i -= F2H_N0) < F2H_N1)   { s = s1; d = d1; }
    else if ((i -= F2H_N1) < F2H_N2)   { s = s2; d = d2; }
    else if ((i -= F2H_N2) < F2H_N3)   { s = s3; d = d3; }
    else { i -= F2H_N3;                  s = s4; d = d4; }
    float4 v0 = *reinterpret_cast<const float4*>(s + i);
    float4 v1 = *reinterpret_cast<const float4*>(s + i + 4);
    __half2 hv[4] = { __floats2half2_rn(v0.x, v0.y), __floats2half2_rn(v0.z, v0.w),
                      __floats2half2_rn(v1.x, v1.y), __floats2half2_rn(v1.z, v1.w) };
    *reinterpret_cast<uint4*>(d + i) = *reinterpret_cast<uint4*>(hv);
}

// Warp-per-row RMSNorm + RoPE; q rows pre-scaled by ATTN_SCALE*log2(e).
__global__ __launch_bounds__(256) void rmsnorm_rope_h(
    __half* __restrict__ xq, const float* __restrict__ wq,
    __half* __restrict__ xk, const float* __restrict__ wk,
    const int* __restrict__ pos)
{
    int widx = threadIdx.x >> 5, lane = threadIdx.x & 31;
    int ridx = blockIdx.x * 8 + widx;
    __half* row;
    const float* w;
    int t;
    float sc;
    if (ridx < SEQ * NHEAD) {
        t = ridx >> 4;
        int h = ridx & 15;
        row = xq + (size_t)t * QROW + (size_t)h * 512;
        w = wq;
        sc = ATTN_SCALE_L2E;
    } else {
        int r2 = ridx - SEQ * NHEAD;
        t = r2 >> 1;
        int h = r2 & 1;
        row = xk + (size_t)t * KROW + (size_t)h * HD;
        w = wk;
        sc = 1.0f;
    }

    uint4 raw = *reinterpret_cast<const uint4*>(row + lane * 8);
    __half2 hv[4];
    *reinterpret_cast<uint4*>(hv) = raw;
    float v[8];
    #pragma unroll
    for (int j = 0; j < 4; j++) {
        float2 f = __half22float2(hv[j]);
        v[2 * j] = f.x; v[2 * j + 1] = f.y;
    }
    float s = 0.f;
    #pragma unroll
    for (int j = 0; j < 8; j++) s += v[j] * v[j];
    #pragma unroll
    for (int o = 16; o; o >>= 1) s += __shfl_xor_sync(0xffffffffu, s, o);
    float rinv = rsqrtf(s * (1.0f / 256.0f) + 1e-6f) * sc;

    float4 w1 = *reinterpret_cast<const float4*>(w + lane * 8);
    float4 w2 = *reinterpret_cast<const float4*>(w + lane * 8 + 4);
    float y[8] = { v[0] * rinv * (1.0f + w1.x), v[1] * rinv * (1.0f + w1.y),
                   v[2] * rinv * (1.0f + w1.z), v[3] * rinv * (1.0f + w1.w),
                   v[4] * rinv * (1.0f + w2.x), v[5] * rinv * (1.0f + w2.y),
                   v[6] * rinv * (1.0f + w2.z), v[7] * rinv * (1.0f + w2.w) };

    float oth[8];
    #pragma unroll
    for (int j = 0; j < 8; j++) oth[j] = __shfl_xor_sync(0xffffffffu, y[j], 4);
    if (lane < 8) {
        float p = (float)pos[t];
        #pragma unroll
        for (int j = 0; j < 8; j++) {
            int d = lane * 8 + j;
            int fi = d & 31;
            float inv = expf(-(float)fi * (16.118095650958322f / 32.0f));
            float sn, cs;
            sincosf(p * inv, &sn, &cs);
            if (lane < 4) y[j] = y[j] * cs - oth[j] * sn;
            else          y[j] = y[j] * cs + oth[j] * sn;
        }
    }
    #pragma unroll
    for (int j = 0; j < 4; j++) hv[j] = __floats2half2_rn(y[2 * j], y[2 * j + 1]);
    *reinterpret_cast<uint4*>(row + lane * 8) = *reinterpret_cast<uint4*>(hv);
}

// ============================ host launch ==================================
extern "C" void kernel_launch(void* const* d_in, const int* in_sizes, int n_in,
                              void* d_out, int out_size)
{
    const int*   positions = (const int*)d_in[0];
    const float* hs  = (const float*)d_in[1];
    const float* wq  = (const float*)d_in[2];
    const float* wk  = (const float*)d_in[3];
    const float* wv  = (const float*)d_in[4];
    const float* wo  = (const float*)d_in[5];
    const float* qnw = (const float*)d_in[6];
    const float* knw = (const float*)d_in[7];
    float* out = (float*)d_out;

    __half *hhs, *hwq, *hwk, *hwv, *hwo, *hq, *hk, *hvt, *ho;
    cudaGetSymbolAddress((void**)&hhs, g_hs_h);
    cudaGetSymbolAddress((void**)&hwq, g_wq_h);
    cudaGetSymbolAddress((void**)&hwk, g_wk_h);
    cudaGetSymbolAddress((void**)&hwv, g_wv_h);
    cudaGetSymbolAddress((void**)&hwo, g_wo_h);
    cudaGetSymbolAddress((void**)&hq,  g_qout_h);
    cudaGetSymbolAddress((void**)&hk,  g_kbuf_h);
    cudaGetSymbolAddress((void**)&hvt, g_vt_h);
    cudaGetSymbolAddress((void**)&ho,  g_obuf_h);

    cudaFuncSetAttribute(hgemm_nt<false>,
                         cudaFuncAttributeMaxDynamicSharedMemorySize, SMEM_BYTES);
    cudaFuncSetAttribute(hgemm_qkv,
                         cudaFuncAttributeMaxDynamicSharedMemorySize, SMEM2_BYTES);
    cudaFuncSetAttribute(flash_attn,
                         cudaFuncAttributeMaxDynamicSharedMemorySize, FSMEM);

    dim3 blk(256);

    // 0) fp32 -> fp16 (single launch, all five buffers, 8 elems/thread)
    f2h_all<<<(int)((F2H_TOT / 8 + 255) / 256), 256>>>(
        hs, hhs, wq, hwq, wk, hwk, wv, hwv, wo, hwo);

    // 1) Q + K + V^T projections (576 CTAs, 128x256 tiles, 64x64 warp tiles)
    hgemm_qkv<<<576, blk, SMEM2_BYTES>>>(hhs, hwq, hwk, hwv, hq, hk, hvt);

    // 2) RMSNorm + RoPE (q rows pre-scaled, k rows plain; one launch)
    rmsnorm_rope_h<<<(SEQ * NHEAD + SEQ * NKV) / 8, 256>>>(
        hq, qnw, hk, knw, positions);

    // 3) Fused flash attention (scores + softmax + PV + gate)
    flash_attn<<<256, blk, FSMEM>>>(hq, hk, hvt, ho);

    // 4) Output projection (f32 out): out = ho @ wo^T
    hgemm_nt<false><<<dim3(HIDDEN / 128, SEQ / 128, 1), blk, SMEM_BYTES>>>(
        ho, hwo, out, ODIM, ODIM, ODIM, HIDDEN);
}

// round 16
// speedup vs baseline: 1.0923x; 1.0923x over previous
#include <cuda_runtime.h>
#include <cuda_fp16.h>
#include <math.h>
#include <stdint.h>

static constexpr int SEQ    = 2048;
static constexpr int HIDDEN = 2048;
static constexpr int NHEAD  = 16;
static constexpr int NKV    = 2;
static constexpr int HD     = 256;
static constexpr int QROW   = NHEAD * HD * 2;   // 8192
static constexpr int KROW   = NKV * HD;         // 512
static constexpr int ODIM   = NHEAD * HD;       // 4096
static constexpr float ATTN_SCALE_L2E = 0.0625f * 1.4426950408889634f;
static constexpr float MASKV = -1e30f;

// ---- scratch (static device memory; no allocations allowed) ----
__device__ __half g_hs_h  [(size_t)SEQ * HIDDEN];
__device__ __half g_wq_h  [(size_t)QROW * HIDDEN];
__device__ __half g_wk_h  [(size_t)KROW * HIDDEN];
__device__ __half g_wv_h  [(size_t)KROW * HIDDEN];
__device__ __half g_wo_h  [(size_t)HIDDEN * ODIM];
__device__ __half g_qout_h[(size_t)SEQ * QROW];
__device__ __half g_kbuf_h[(size_t)SEQ * KROW];
__device__ __half g_vt_h  [(size_t)KROW * SEQ];
__device__ __half g_obuf_h[(size_t)SEQ * ODIM];

// ============================ asm helpers ==================================
__device__ __forceinline__ uint32_t smem_u32(const void* p) {
    uint32_t a;
    asm("{ .reg .u64 t; cvta.to.shared.u64 t, %1; cvt.u32.u64 %0, t; }" : "=r"(a) : "l"(p));
    return a;
}
#define CP_ASYNC16(dst, src) \
    asm volatile("cp.async.cg.shared.global [%0], [%1], 16;" :: "r"(dst), "l"(src))
#define CP_COMMIT() asm volatile("cp.async.commit_group;")
#define CP_WAIT(n)  asm volatile("cp.async.wait_group %0;" :: "n"(n))

__device__ __forceinline__ void ldm_x4(uint32_t* r, uint32_t addr) {
    asm volatile("ldmatrix.sync.aligned.m8n8.x4.shared.b16 {%0,%1,%2,%3}, [%4];"
                 : "=r"(r[0]), "=r"(r[1]), "=r"(r[2]), "=r"(r[3]) : "r"(addr));
}
__device__ __forceinline__ void mma_f16(float* c, const uint32_t* a, const uint32_t* b) {
    asm volatile(
        "mma.sync.aligned.m16n8k16.row.col.f32.f16.f16.f32 "
        "{%0,%1,%2,%3}, {%4,%5,%6,%7}, {%8,%9}, {%0,%1,%2,%3};"
        : "+f"(c[0]), "+f"(c[1]), "+f"(c[2]), "+f"(c[3])
        : "r"(a[0]), "r"(a[1]), "r"(a[2]), "r"(a[3]), "r"(b[0]), "r"(b[1]));
}
__device__ __forceinline__ uint32_t h2u(__half2 v) {
    return *reinterpret_cast<uint32_t*>(&v);
}

// ======================= fp16 NT GEMM (cp.async + ldmatrix) ================
static constexpr int PIPE_S = 4;
static constexpr int STAGE_BYTES = 16384;
static constexpr int SMEM_BYTES  = PIPE_S * STAGE_BYTES;   // 64 KB

template<bool HALF_OUT>
__device__ __forceinline__ void hgemm_body(
    const __half* __restrict__ A, const __half* __restrict__ B, void* __restrict__ Cv,
    int m0, int n0, int K, int lda, int ldb, int ldc)
{
    int nk = K >> 5;
    extern __shared__ char smem[];
    uint32_t sb = smem_u32(smem);
    int tid = threadIdx.x, lane = tid & 31, wid = tid >> 5;
    int wm = wid >> 1, wn = wid & 1;
    int grp = lane >> 3, l7 = lane & 7;

    auto fill = [&](int st, int kt) {
        int k0 = kt << 5;
        uint32_t base = sb + st * STAGE_BYTES;
        #pragma unroll
        for (int i = 0; i < 2; i++) {
            int id = tid + i * 256, r = id >> 2, c = id & 3;
            CP_ASYNC16(base + r * 64 + ((c ^ ((r >> 1) & 3)) << 4),
                       A + (long long)(m0 + r) * lda + k0 + c * 8);
        }
        #pragma unroll
        for (int i = 0; i < 2; i++) {
            int id = tid + i * 256, r = id >> 2, c = id & 3;
            CP_ASYNC16(base + 8192 + r * 64 + ((c ^ ((r >> 1) & 3)) << 4),
                       B + (long long)(n0 + r) * ldb + k0 + c * 8);
        }
    };

    float acc[2][8][4] = {};

    #pragma unroll
    for (int st = 0; st < PIPE_S - 1; st++) {
        if (st < nk) fill(st, st);
        CP_COMMIT();
    }

    for (int kt = 0; kt < nk; kt++) {
        CP_WAIT(PIPE_S - 2);
        __syncthreads();
        if (kt + PIPE_S - 1 < nk) fill((kt + PIPE_S - 1) & 3, kt + PIPE_S - 1);
        CP_COMMIT();

        uint32_t abase = sb + (kt & 3) * STAGE_BYTES;
        uint32_t bbase = abase + 8192;
        #pragma unroll
        for (int s = 0; s < 2; s++) {
            uint32_t af[2][4], bf[4][4];
            #pragma unroll
            for (int mt = 0; mt < 2; mt++) {
                int row = wm * 32 + mt * 16 + l7 + ((grp & 1) << 3);
                int ch  = s * 2 + (grp >> 1);
                ldm_x4(af[mt], abase + row * 64 + ((ch ^ ((row >> 1) & 3)) << 4));
            }
            #pragma unroll
            for (int nt = 0; nt < 4; nt++) {
                int row = wn * 64 + nt * 16 + l7 + ((grp >> 1) << 3);
                int ch  = s * 2 + (grp & 1);
                ldm_x4(bf[nt], bbase + row * 64 + ((ch ^ ((row >> 1) & 3)) << 4));
            }
            #pragma unroll
            for (int mt = 0; mt < 2; mt++)
                #pragma unroll
                for (int nt = 0; nt < 4; nt++) {
                    mma_f16(acc[mt][nt * 2],     af[mt], &bf[nt][0]);
                    mma_f16(acc[mt][nt * 2 + 1], af[mt], &bf[nt][2]);
                }
        }
    }

    int g8 = lane >> 2, t2 = (lane & 3) * 2;
    #pragma unroll
    for (int mt = 0; mt < 2; mt++) {
        #pragma unroll
        for (int nt = 0; nt < 8; nt++) {
            long long row = m0 + wm * 32 + mt * 16 + g8;
            int col = n0 + wn * 64 + nt * 8 + t2;
            if (HALF_OUT) {
                __half* C = (__half*)Cv;
                *(__half2*)(C + row * ldc + col) =
                    __floats2half2_rn(acc[mt][nt][0], acc[mt][nt][1]);
                *(__half2*)(C + (row + 8) * ldc + col) =
                    __floats2half2_rn(acc[mt][nt][2], acc[mt][nt][3]);
            } else {
                float* C = (float*)Cv;
                *(float2*)(C + row * ldc + col) =
                    make_float2(acc[mt][nt][0], acc[mt][nt][1]);
                *(float2*)(C + (row + 8) * ldc + col) =
                    make_float2(acc[mt][nt][2], acc[mt][nt][3]);
            }
        }
    }
}

template<bool HALF_OUT>
__global__ __launch_bounds__(256, 2) void hgemm_nt(
    const __half* __restrict__ A, const __half* __restrict__ B, void* __restrict__ Cv,
    int K, int lda, int ldb, int ldc)
{
    hgemm_body<HALF_OUT>(A, B, Cv, blockIdx.y * 128, blockIdx.x * 128, K, lda, ldb, ldc);
}

// Combined Q + K + V^T projections in ONE launch (1152 CTAs).
__global__ __launch_bounds__(256, 2) void hgemm_qkv(
    const __half* __restrict__ hs,  const __half* __restrict__ wq,
    const __half* __restrict__ wk,  const __half* __restrict__ wv,
    __half* __restrict__ qout, __half* __restrict__ kout, __half* __restrict__ vtout)
{
    int b = blockIdx.x;
    if (b < 1024) {            // qout = hs @ wq^T   [2048 x 8192]
        hgemm_body<true>(hs, wq, qout, (b >> 6) << 7, (b & 63) << 7,
                         HIDDEN, HIDDEN, HIDDEN, QROW);
    } else if (b < 1088) {     // kout = hs @ wk^T   [2048 x 512]
        int c = b - 1024;
        hgemm_body<true>(hs, wk, kout, (c >> 2) << 7, (c & 3) << 7,
                         HIDDEN, HIDDEN, HIDDEN, KROW);
    } else {                   // vtout = wv @ hs^T  [512 x 2048]
        int c = b - 1088;
        hgemm_body<true>(wv, hs, vtout, (c >> 4) << 7, (c & 15) << 7,
                         HIDDEN, HIDDEN, HIDDEN, SEQ);
    }
}

// ======================= fused flash attention =============================
// CTA: 128 q-rows x 1 head, 8 warps; warp = 16q x full 256d (best measured).
// Q pre-scaled by ATTN_SCALE*log2(e) in rmsnorm -> no per-iter scale.
// Online softmax in log2 domain; kc-outer PV; exact rescale skip.
static constexpr int FQ_BYTES = 128 * 512;
static constexpr int FK_BYTES = 64 * 512;
static constexpr int FSTAGE   = FK_BYTES + 256 * 128;      // 65536
static constexpr int FSMEM    = FQ_BYTES + 2 * FSTAGE;     // 196608

__global__ __launch_bounds__(256, 1) void flash_attn(
    const __half* __restrict__ Qh, const __half* __restrict__ Kh,
    const __half* __restrict__ Vth, __half* __restrict__ O)
{
    int bx = blockIdx.x;
    int qt = 15 - (bx >> 4);          // heavy q-tiles first
    int h  = bx & 15;
    int q0 = qt << 7;
    int kv = h >> 3;
    int niter = (qt + 1) << 1;

    extern __shared__ char smem[];
    uint32_t sq = smem_u32(smem);

    int tid = threadIdx.x, lane = tid & 31, wid = tid >> 5;
    int grp = lane >> 3, l7 = lane & 7;
    int g8 = lane >> 2, t2 = (lane & 3) << 1;

    #pragma unroll
    for (int i = 0; i < 16; i++) {
        int id = tid + (i << 8);
        int r = id >> 5, c = id & 31;
        CP_ASYNC16(sq + r * 512 + ((c ^ (r & 7)) << 4),
                   Qh + (size_t)(q0 + r) * QROW + h * 512 + c * 8);
    }
    auto fillKV = [&](int it, int st) {
        int k0 = it << 6;
        uint32_t kb = sq + FQ_BYTES + st * FSTAGE;
        uint32_t vb = kb + FK_BYTES;
        #pragma unroll
        for (int i = 0; i < 8; i++) {
            int id = tid + (i << 8);
            int r = id >> 5, c = id & 31;
            CP_ASYNC16(kb + r * 512 + ((c ^ (r & 7)) << 4),
                       Kh + (size_t)(k0 + r) * KROW + kv * 256 + c * 8);
        }
        #pragma unroll
        for (int i = 0; i < 8; i++) {
            int id = tid + (i << 8);
            int d = id >> 3, c = id & 7;
            CP_ASYNC16(vb + d * 128 + ((c ^ (d & 7)) << 4),
                       Vth + (size_t)(kv * 256 + d) * SEQ + k0 + c * 8);
        }
    };
    fillKV(0, 0);
    CP_COMMIT();
    if (niter > 1) { fillKV(1, 1); CP_COMMIT(); }

    float m0 = MASKV, m1 = MASKV, l0 = 0.f, l1 = 0.f;   // log2 domain
    float accO[32][4] = {};
    int qrow0 = q0 + wid * 16 + g8;

    for (int it = 0; it < niter; it++) {
        int k0 = it << 6;
        if (it + 1 < niter) { CP_WAIT(1); } else { CP_WAIT(0); }
        __syncthreads();

        uint32_t kb = sq + FQ_BYTES + (it & 1) * FSTAGE;
        uint32_t vb = kb + FK_BYTES;

        // ---- S = Q K^T (Q pre-scaled) ----
        float accS[8][4] = {};
        #pragma unroll
        for (int s = 0; s < 16; s++) {
            uint32_t af[4];
            int qr = wid * 16 + l7 + ((grp & 1) << 3);
            int ch = s * 2 + (grp >> 1);
            ldm_x4(af, sq + qr * 512 + ((ch ^ (qr & 7)) << 4));
            #pragma unroll
            for (int np = 0; np < 4; np++) {
                uint32_t bf[4];
                int kr = np * 16 + l7 + ((grp >> 1) << 3);
                int c2 = s * 2 + (grp & 1);
                ldm_x4(bf, kb + kr * 512 + ((c2 ^ (kr & 7)) << 4));
                mma_f16(accS[np * 2],     af, &bf[0]);
                mma_f16(accS[np * 2 + 1], af, &bf[2]);
            }
        }

        if (k0 + 63 > q0 + wid * 16) {       // causal mask (diagonal tiles)
            #pragma unroll
            for (int nt = 0; nt < 8; nt++) {
                int c0 = k0 + nt * 8 + t2;
                if (c0 > qrow0)         accS[nt][0] = MASKV;
                if (c0 + 1 > qrow0)     accS[nt][1] = MASKV;
                if (c0 > qrow0 + 8)     accS[nt][2] = MASKV;
                if (c0 + 1 > qrow0 + 8) accS[nt][3] = MASKV;
            }
        }

        // ---- online softmax (log2 domain) ----
        float mx0 = MASKV, mx1 = MASKV;
        #pragma unroll
        for (int nt = 0; nt < 8; nt++) {
            mx0 = fmaxf(mx0, fmaxf(accS[nt][0], accS[nt][1]));
            mx1 = fmaxf(mx1, fmaxf(accS[nt][2], accS[nt][3]));
        }
        mx0 = fmaxf(mx0, __shfl_xor_sync(0xffffffffu, mx0, 1));
        mx0 = fmaxf(mx0, __shfl_xor_sync(0xffffffffu, mx0, 2));
        mx1 = fmaxf(mx1, __shfl_xor_sync(0xffffffffu, mx1, 1));
        mx1 = fmaxf(mx1, __shfl_xor_sync(0xffffffffu, mx1, 2));

        float mn0 = fmaxf(m0, mx0), mn1 = fmaxf(m1, mx1);
        int need = __any_sync(0xffffffffu, (mn0 != m0) || (mn1 != m1));
        float a0 = exp2f(m0 - mn0), a1 = exp2f(m1 - mn1);
        m0 = mn0; m1 = mn1;
        float s0 = 0.f, s1 = 0.f;
        #pragma unroll
        for (int nt = 0; nt < 8; nt++) {
            accS[nt][0] = exp2f(accS[nt][0] - mn0); s0 += accS[nt][0];
            accS[nt][1] = exp2f(accS[nt][1] - mn0); s0 += accS[nt][1];
            accS[nt][2] = exp2f(accS[nt][2] - mn1); s1 += accS[nt][2];
            accS[nt][3] = exp2f(accS[nt][3] - mn1); s1 += accS[nt][3];
        }
        s0 += __shfl_xor_sync(0xffffffffu, s0, 1);
        s0 += __shfl_xor_sync(0xffffffffu, s0, 2);
        s1 += __shfl_xor_sync(0xffffffffu, s1, 1);
        s1 += __shfl_xor_sync(0xffffffffu, s1, 2);
        l0 = l0 * a0 + s0;
        l1 = l1 * a1 + s1;
        if (need) {   // exact skip: a == 1 when no row max changed
            #pragma unroll
            for (int nt = 0; nt < 32; nt++) {
                accO[nt][0] *= a0; accO[nt][1] *= a0;
                accO[nt][2] *= a1; accO[nt][3] *= a1;
            }
        }

        // ---- P fragments (S accum layout == A operand layout) ----
        uint32_t pf[4][4];
        #pragma unroll
        for (int kc = 0; kc < 4; kc++) {
            pf[kc][0] = h2u(__floats2half2_rn(accS[2 * kc][0],     accS[2 * kc][1]));
            pf[kc][1] = h2u(__floats2half2_rn(accS[2 * kc][2],     accS[2 * kc][3]));
            pf[kc][2] = h2u(__floats2half2_rn(accS[2 * kc + 1][0], accS[2 * kc + 1][1]));
            pf[kc][3] = h2u(__floats2half2_rn(accS[2 * kc + 1][2], accS[2 * kc + 1][3]));
        }

        // ---- O += P V (kc outer) ----
        #pragma unroll
        for (int kc = 0; kc < 4; kc++) {
            #pragma unroll
            for (int np = 0; np < 16; np++) {
                uint32_t bf[4];
                int dr = np * 16 + l7 + ((grp >> 1) << 3);
                int ch = kc * 2 + (grp & 1);
                ldm_x4(bf, vb + dr * 128 + ((ch ^ (dr & 7)) << 4));
                mma_f16(accO[np * 2],     pf[kc], &bf[0]);
                mma_f16(accO[np * 2 + 1], pf[kc], &bf[2]);
            }
        }

        __syncthreads();
        if (it + 2 < niter) { fillKV(it + 2, it & 1); CP_COMMIT(); }
    }

    // ---- epilogue: 1/l, sigmoid gate, fp16 store ----
    float r0 = 1.f / l0, r1 = 1.f / l1;
    int trow0 = qrow0, trow1 = qrow0 + 8;
    const __half* G0 = Qh + (size_t)trow0 * QROW + h * 512 + 256;
    const __half* G1 = Qh + (size_t)trow1 * QROW + h * 512 + 256;
    __half* O0 = O + (size_t)trow0 * ODIM + h * 256;
    __half* O1 = O + (size_t)trow1 * ODIM + h * 256;
    #pragma unroll
    for (int nt = 0; nt < 32; nt++) {
        int d = nt * 8 + t2;
        float2 ga = __half22float2(*(const __half2*)(G0 + d));
        float2 gb = __half22float2(*(const __half2*)(G1 + d));
        float vx = accO[nt][0] * r0 / (1.f + __expf(-ga.x));
        float vy = accO[nt][1] * r0 / (1.f + __expf(-ga.y));
        float wx = accO[nt][2] * r1 / (1.f + __expf(-gb.x));
        float wy = accO[nt][3] * r1 / (1.f + __expf(-gb.y));
        *(__half2*)(O0 + d) = __floats2half2_rn(vx, vy);
        *(__half2*)(O1 + d) = __floats2half2_rn(wx, wy);
    }
}

// ============================ elementwise kernels ==========================
static constexpr long long F2H_N0 = (long long)SEQ * HIDDEN;
static constexpr long long F2H_N1 = (long long)QROW * HIDDEN;
static constexpr long long F2H_N2 = (long long)KROW * HIDDEN;
static constexpr long long F2H_N3 = (long long)KROW * HIDDEN;
static constexpr long long F2H_N4 = (long long)HIDDEN * ODIM;
static constexpr long long F2H_TOT = F2H_N0 + F2H_N1 + F2H_N2 + F2H_N3 + F2H_N4;

// 8 elements per thread: 2x LDG.128 -> 1x STG.128.
__global__ __launch_bounds__(256) void f2h_all(
    const float* __restrict__ s0, __half* __restrict__ d0,
    const float* __restrict__ s1, __half* __restrict__ d1,
    const float* __restrict__ s2, __half* __restrict__ d2,
    const float* __restrict__ s3, __half* __restrict__ d3,
    const float* __restrict__ s4, __half* __restrict__ d4)
{
    long long i = ((long long)blockIdx.x * 256 + threadIdx.x) * 8;
    if (i >= F2H_TOT) return;
    const float* s;
    __half* d;
    if (i < F2H_N0)                    { s = s0; d = d0; }
    else if ((i -= F2H_N0) < F2H_N1)   { s = s1; d = d1; }
    else if ((i -= F2H_N1) < F2H_N2)   { s = s2; d = d2; }
    else if ((i -= F2H_N2) < F2H_N3)   { s = s3; d = d3; }
    else { i -= F2H_N3;                  s = s4; d = d4; }
    float4 v0 = *reinterpret_cast<const float4*>(s + i);
    float4 v1 = *reinterpret_cast<const float4*>(s + i + 4);
    __half2 hv[4] = { __floats2half2_rn(v0.x, v0.y), __floats2half2_rn(v0.z, v0.w),
                      __floats2half2_rn(v1.x, v1.y), __floats2half2_rn(v1.z, v1.w) };
    *reinterpret_cast<uint4*>(d + i) = *reinterpret_cast<uint4*>(hv);
}

// Warp-per-row RMSNorm + RoPE; q rows pre-scaled by ATTN_SCALE*log2(e).
__global__ __launch_bounds__(256) void rmsnorm_rope_h(
    __half* __restrict__ xq, const float* __restrict__ wq,
    __half* __restrict__ xk, const float* __restrict__ wk,
    const int* __restrict__ pos)
{
    int widx = threadIdx.x >> 5, lane = threadIdx.x & 31;
    int ridx = blockIdx.x * 8 + widx;
    __half* row;
    const float* w;
    int t;
    float sc;
    if (ridx < SEQ * NHEAD) {
        t = ridx >> 4;
        int h = ridx & 15;
        row = xq + (size_t)t * QROW + (size_t)h * 512;
        w = wq;
        sc = ATTN_SCALE_L2E;
    } else {
        int r2 = ridx - SEQ * NHEAD;
        t = r2 >> 1;
        int h = r2 & 1;
        row = xk + (size_t)t * KROW + (size_t)h * HD;
        w = wk;
        sc = 1.0f;
    }

    uint4 raw = *reinterpret_cast<const uint4*>(row + lane * 8);
    __half2 hv[4];
    *reinterpret_cast<uint4*>(hv) = raw;
    float v[8];
    #pragma unroll
    for (int j = 0; j < 4; j++) {
        float2 f = __half22float2(hv[j]);
        v[2 * j] = f.x; v[2 * j + 1] = f.y;
    }
    float s = 0.f;
    #pragma unroll
    for (int j = 0; j < 8; j++) s += v[j] * v[j];
    #pragma unroll
    for (int o = 16; o; o >>= 1) s += __shfl_xor_sync(0xffffffffu, s, o);
    float rinv = rsqrtf(s * (1.0f / 256.0f) + 1e-6f) * sc;

    float4 w1 = *reinterpret_cast<const float4*>(w + lane * 8);
    float4 w2 = *reinterpret_cast<const float4*>(w + lane * 8 + 4);
    float y[8] = { v[0] * rinv * (1.0f + w1.x), v[1] * rinv * (1.0f + w1.y),
                   v[2] * rinv * (1.0f + w1.z), v[3] * rinv * (1.0f + w1.w),
                   v[4] * rinv * (1.0f + w2.x), v[5] * rinv * (1.0f + w2.y),
                   v[6] * rinv * (1.0f + w2.z), v[7] * rinv * (1.0f + w2.w) };

    float oth[8];
    #pragma unroll
    for (int j = 0; j < 8; j++) oth[j] = __shfl_xor_sync(0xffffffffu, y[j], 4);
    if (lane < 8) {
        float p = (float)pos[t];
        #pragma unroll
        for (int j = 0; j < 8; j++) {
            int d = lane * 8 + j;
            int fi = d & 31;
            float inv = expf(-(float)fi * (16.118095650958322f / 32.0f));
            float sn, cs;
            sincosf(p * inv, &sn, &cs);
            if (lane < 4) y[j] = y[j] * cs - oth[j] * sn;
            else          y[j] = y[j] * cs + oth[j] * sn;
        }
    }
    #pragma unroll
    for (int j = 0; j < 4; j++) hv[j] = __floats2half2_rn(y[2 * j], y[2 * j + 1]);
    *reinterpret_cast<uint4*>(row + lane * 8) = *reinterpret_cast<uint4*>(hv);
}

// ============================ host launch ==================================
extern "C" void kernel_launch(void* const* d_in, const int* in_sizes, int n_in,
                              void* d_out, int out_size)
{
    const int*   positions = (const int*)d_in[0];
    const float* hs  = (const float*)d_in[1];
    const float* wq  = (const float*)d_in[2];
    const float* wk  = (const float*)d_in[3];
    const float* wv  = (const float*)d_in[4];
    const float* wo  = (const float*)d_in[5];
    const float* qnw = (const float*)d_in[6];
    const float* knw = (const float*)d_in[7];
    float* out = (float*)d_out;

    __half *hhs, *hwq, *hwk, *hwv, *hwo, *hq, *hk, *hvt, *ho;
    cudaGetSymbolAddress((void**)&hhs, g_hs_h);
    cudaGetSymbolAddress((void**)&hwq, g_wq_h);
    cudaGetSymbolAddress((void**)&hwk, g_wk_h);
    cudaGetSymbolAddress((void**)&hwv, g_wv_h);
    cudaGetSymbolAddress((void**)&hwo, g_wo_h);
    cudaGetSymbolAddress((void**)&hq,  g_qout_h);
    cudaGetSymbolAddress((void**)&hk,  g_kbuf_h);
    cudaGetSymbolAddress((void**)&hvt, g_vt_h);
    cudaGetSymbolAddress((void**)&ho,  g_obuf_h);

    cudaFuncSetAttribute(hgemm_nt<false>,
                         cudaFuncAttributeMaxDynamicSharedMemorySize, SMEM_BYTES);
    cudaFuncSetAttribute(hgemm_qkv,
                         cudaFuncAttributeMaxDynamicSharedMemorySize, SMEM_BYTES);
    cudaFuncSetAttribute(flash_attn,
                         cudaFuncAttributeMaxDynamicSharedMemorySize, FSMEM);

    dim3 blk(256);

    // 0) fp32 -> fp16 (single launch, all five buffers, 8 elems/thread)
    f2h_all<<<(int)((F2H_TOT / 8 + 255) / 256), 256>>>(
        hs, hhs, wq, hwq, wk, hwk, wv, hwv, wo, hwo);

    // 1) Q + K + V^T projections (one launch, 1152 CTAs, 128x128 tiles)
    hgemm_qkv<<<1152, blk, SMEM_BYTES>>>(hhs, hwq, hwk, hwv, hq, hk, hvt);

    // 2) RMSNorm + RoPE (q rows pre-scaled, k rows plain; one launch)
    rmsnorm_rope_h<<<(SEQ * NHEAD + SEQ * NKV) / 8, 256>>>(
        hq, qnw, hk, knw, positions);

    // 3) Fused flash attention (scores + softmax + PV + gate)
    flash_attn<<<256, blk, FSMEM>>>(hq, hk, hvt, ho);

    // 4) Output projection (f32 out): out = ho @ wo^T
    hgemm_nt<false><<<dim3(HIDDEN / 128, SEQ / 128, 1), blk, SMEM_BYTES>>>(
        ho, hwo, out, ODIM, ODIM, ODIM, HIDDEN);
}

// round 17
// speedup vs baseline: 1.1022x; 1.0091x over previous
#include <cuda_runtime.h>
#include <cuda_fp16.h>
#include <math.h>
#include <stdint.h>

static constexpr int SEQ    = 2048;
static constexpr int HIDDEN = 2048;
static constexpr int NHEAD  = 16;
static constexpr int NKV    = 2;
static constexpr int HD     = 256;
static constexpr int QROW   = NHEAD * HD * 2;   // 8192
static constexpr int KROW   = NKV * HD;         // 512
static constexpr int ODIM   = NHEAD * HD;       // 4096
static constexpr float ATTN_SCALE_L2E = 0.0625f * 1.4426950408889634f;
static constexpr float MASKV = -1e30f;

// ---- scratch (static device memory; no allocations allowed) ----
__device__ __half g_hs_h  [(size_t)SEQ * HIDDEN];
__device__ __half g_wq_h  [(size_t)QROW * HIDDEN];
__device__ __half g_wk_h  [(size_t)KROW * HIDDEN];
__device__ __half g_wv_h  [(size_t)KROW * HIDDEN];
__device__ __half g_wo_h  [(size_t)HIDDEN * ODIM];
__device__ __half g_qout_h[(size_t)SEQ * QROW];
__device__ __half g_kbuf_h[(size_t)SEQ * KROW];
__device__ __half g_vt_h  [(size_t)KROW * SEQ];
__device__ __half g_obuf_h[(size_t)SEQ * ODIM];
__device__ float  g_ropec [(size_t)SEQ * 32];   // cos[token][freq]
__device__ float  g_ropes [(size_t)SEQ * 32];   // sin[token][freq]

// ============================ asm helpers ==================================
__device__ __forceinline__ uint32_t smem_u32(const void* p) {
    uint32_t a;
    asm("{ .reg .u64 t; cvta.to.shared.u64 t, %1; cvt.u32.u64 %0, t; }" : "=r"(a) : "l"(p));
    return a;
}
#define CP_ASYNC16(dst, src) \
    asm volatile("cp.async.cg.shared.global [%0], [%1], 16;" :: "r"(dst), "l"(src))
#define CP_COMMIT() asm volatile("cp.async.commit_group;")
#define CP_WAIT(n)  asm volatile("cp.async.wait_group %0;" :: "n"(n))

__device__ __forceinline__ void ldm_x4(uint32_t* r, uint32_t addr) {
    asm volatile("ldmatrix.sync.aligned.m8n8.x4.shared.b16 {%0,%1,%2,%3}, [%4];"
                 : "=r"(r[0]), "=r"(r[1]), "=r"(r[2]), "=r"(r[3]) : "r"(addr));
}
__device__ __forceinline__ void mma_f16(float* c, const uint32_t* a, const uint32_t* b) {
    asm volatile(
        "mma.sync.aligned.m16n8k16.row.col.f32.f16.f16.f32 "
        "{%0,%1,%2,%3}, {%4,%5,%6,%7}, {%8,%9}, {%0,%1,%2,%3};"
        : "+f"(c[0]), "+f"(c[1]), "+f"(c[2]), "+f"(c[3])
        : "r"(a[0]), "r"(a[1]), "r"(a[2]), "r"(a[3]), "r"(b[0]), "r"(b[1]));
}
__device__ __forceinline__ uint32_t h2u(__half2 v) {
    return *reinterpret_cast<uint32_t*>(&v);
}

// ======================= fp16 NT GEMM (cp.async + ldmatrix) ================
static constexpr int PIPE_S = 4;
static constexpr int STAGE_BYTES = 16384;
static constexpr int SMEM_BYTES  = PIPE_S * STAGE_BYTES;   // 64 KB

template<bool HALF_OUT>
__device__ __forceinline__ void hgemm_body(
    const __half* __restrict__ A, const __half* __restrict__ B, void* __restrict__ Cv,
    int m0, int n0, int K, int lda, int ldb, int ldc)
{
    int nk = K >> 5;
    extern __shared__ char smem[];
    uint32_t sb = smem_u32(smem);
    int tid = threadIdx.x, lane = tid & 31, wid = tid >> 5;
    int wm = wid >> 1, wn = wid & 1;
    int grp = lane >> 3, l7 = lane & 7;

    auto fill = [&](int st, int kt) {
        int k0 = kt << 5;
        uint32_t base = sb + st * STAGE_BYTES;
        #pragma unroll
        for (int i = 0; i < 2; i++) {
            int id = tid + i * 256, r = id >> 2, c = id & 3;
            CP_ASYNC16(base + r * 64 + ((c ^ ((r >> 1) & 3)) << 4),
                       A + (long long)(m0 + r) * lda + k0 + c * 8);
        }
        #pragma unroll
        for (int i = 0; i < 2; i++) {
            int id = tid + i * 256, r = id >> 2, c = id & 3;
            CP_ASYNC16(base + 8192 + r * 64 + ((c ^ ((r >> 1) & 3)) << 4),
                       B + (long long)(n0 + r) * ldb + k0 + c * 8);
        }
    };

    float acc[2][8][4] = {};

    #pragma unroll
    for (int st = 0; st < PIPE_S - 1; st++) {
        if (st < nk) fill(st, st);
        CP_COMMIT();
    }

    for (int kt = 0; kt < nk; kt++) {
        CP_WAIT(PIPE_S - 2);
        __syncthreads();
        if (kt + PIPE_S - 1 < nk) fill((kt + PIPE_S - 1) & 3, kt + PIPE_S - 1);
        CP_COMMIT();

        uint32_t abase = sb + (kt & 3) * STAGE_BYTES;
        uint32_t bbase = abase + 8192;
        #pragma unroll
        for (int s = 0; s < 2; s++) {
            uint32_t af[2][4], bf[4][4];
            #pragma unroll
            for (int mt = 0; mt < 2; mt++) {
                int row = wm * 32 + mt * 16 + l7 + ((grp & 1) << 3);
                int ch  = s * 2 + (grp >> 1);
                ldm_x4(af[mt], abase + row * 64 + ((ch ^ ((row >> 1) & 3)) << 4));
            }
            #pragma unroll
            for (int nt = 0; nt < 4; nt++) {
                int row = wn * 64 + nt * 16 + l7 + ((grp >> 1) << 3);
                int ch  = s * 2 + (grp & 1);
                ldm_x4(bf[nt], bbase + row * 64 + ((ch ^ ((row >> 1) & 3)) << 4));
            }
            #pragma unroll
            for (int mt = 0; mt < 2; mt++)
                #pragma unroll
                for (int nt = 0; nt < 4; nt++) {
                    mma_f16(acc[mt][nt * 2],     af[mt], &bf[nt][0]);
                    mma_f16(acc[mt][nt * 2 + 1], af[mt], &bf[nt][2]);
                }
        }
    }

    int g8 = lane >> 2, t2 = (lane & 3) * 2;
    #pragma unroll
    for (int mt = 0; mt < 2; mt++) {
        #pragma unroll
        for (int nt = 0; nt < 8; nt++) {
            long long row = m0 + wm * 32 + mt * 16 + g8;
            int col = n0 + wn * 64 + nt * 8 + t2;
            if (HALF_OUT) {
                __half* C = (__half*)Cv;
                *(__half2*)(C + row * ldc + col) =
                    __floats2half2_rn(acc[mt][nt][0], acc[mt][nt][1]);
                *(__half2*)(C + (row + 8) * ldc + col) =
                    __floats2half2_rn(acc[mt][nt][2], acc[mt][nt][3]);
            } else {
                float* C = (float*)Cv;
                *(float2*)(C + row * ldc + col) =
                    make_float2(acc[mt][nt][0], acc[mt][nt][1]);
                *(float2*)(C + (row + 8) * ldc + col) =
                    make_float2(acc[mt][nt][2], acc[mt][nt][3]);
            }
        }
    }
}

template<bool HALF_OUT>
__global__ __launch_bounds__(256, 2) void hgemm_nt(
    const __half* __restrict__ A, const __half* __restrict__ B, void* __restrict__ Cv,
    int K, int lda, int ldb, int ldc)
{
    hgemm_body<HALF_OUT>(A, B, Cv, blockIdx.y * 128, blockIdx.x * 128, K, lda, ldb, ldc);
}

// Combined Q + K + V^T projections in ONE launch (1152 CTAs).
__global__ __launch_bounds__(256, 2) void hgemm_qkv(
    const __half* __restrict__ hs,  const __half* __restrict__ wq,
    const __half* __restrict__ wk,  const __half* __restrict__ wv,
    __half* __restrict__ qout, __half* __restrict__ kout, __half* __restrict__ vtout)
{
    int b = blockIdx.x;
    if (b < 1024) {            // qout = hs @ wq^T   [2048 x 8192]
        hgemm_body<true>(hs, wq, qout, (b >> 6) << 7, (b & 63) << 7,
                         HIDDEN, HIDDEN, HIDDEN, QROW);
    } else if (b < 1088) {     // kout = hs @ wk^T   [2048 x 512]
        int c = b - 1024;
        hgemm_body<true>(hs, wk, kout, (c >> 2) << 7, (c & 3) << 7,
                         HIDDEN, HIDDEN, HIDDEN, KROW);
    } else {                   // vtout = wv @ hs^T  [512 x 2048]
        int c = b - 1088;
        hgemm_body<true>(wv, hs, vtout, (c >> 4) << 7, (c & 15) << 7,
                         HIDDEN, HIDDEN, HIDDEN, SEQ);
    }
}

// ======================= fused flash attention =============================
// CTA: 128 q-rows x 1 head, 8 warps; warp = 16q x full 256d (best measured).
// Q pre-scaled by ATTN_SCALE*log2(e) in rmsnorm -> no per-iter scale.
// Online softmax in log2 domain; kc-outer PV; exact rescale skip.
static constexpr int FQ_BYTES = 128 * 512;
static constexpr int FK_BYTES = 64 * 512;
static constexpr int FSTAGE   = FK_BYTES + 256 * 128;      // 65536
static constexpr int FSMEM    = FQ_BYTES + 2 * FSTAGE;     // 196608

__global__ __launch_bounds__(256, 1) void flash_attn(
    const __half* __restrict__ Qh, const __half* __restrict__ Kh,
    const __half* __restrict__ Vth, __half* __restrict__ O)
{
    int bx = blockIdx.x;
    int qt = 15 - (bx >> 4);          // heavy q-tiles first
    int h  = bx & 15;
    int q0 = qt << 7;
    int kv = h >> 3;
    int niter = (qt + 1) << 1;

    extern __shared__ char smem[];
    uint32_t sq = smem_u32(smem);

    int tid = threadIdx.x, lane = tid & 31, wid = tid >> 5;
    int grp = lane >> 3, l7 = lane & 7;
    int g8 = lane >> 2, t2 = (lane & 3) << 1;

    #pragma unroll
    for (int i = 0; i < 16; i++) {
        int id = tid + (i << 8);
        int r = id >> 5, c = id & 31;
        CP_ASYNC16(sq + r * 512 + ((c ^ (r & 7)) << 4),
                   Qh + (size_t)(q0 + r) * QROW + h * 512 + c * 8);
    }
    auto fillKV = [&](int it, int st) {
        int k0 = it << 6;
        uint32_t kb = sq + FQ_BYTES + st * FSTAGE;
        uint32_t vb = kb + FK_BYTES;
        #pragma unroll
        for (int i = 0; i < 8; i++) {
            int id = tid + (i << 8);
            int r = id >> 5, c = id & 31;
            CP_ASYNC16(kb + r * 512 + ((c ^ (r & 7)) << 4),
                       Kh + (size_t)(k0 + r) * KROW + kv * 256 + c * 8);
        }
        #pragma unroll
        for (int i = 0; i < 8; i++) {
            int id = tid + (i << 8);
            int d = id >> 3, c = id & 7;
            CP_ASYNC16(vb + d * 128 + ((c ^ (d & 7)) << 4),
                       Vth + (size_t)(kv * 256 + d) * SEQ + k0 + c * 8);
        }
    };
    fillKV(0, 0);
    CP_COMMIT();
    if (niter > 1) { fillKV(1, 1); CP_COMMIT(); }

    float m0 = MASKV, m1 = MASKV, l0 = 0.f, l1 = 0.f;   // log2 domain
    float accO[32][4] = {};
    int qrow0 = q0 + wid * 16 + g8;

    for (int it = 0; it < niter; it++) {
        int k0 = it << 6;
        if (it + 1 < niter) { CP_WAIT(1); } else { CP_WAIT(0); }
        __syncthreads();

        uint32_t kb = sq + FQ_BYTES + (it & 1) * FSTAGE;
        uint32_t vb = kb + FK_BYTES;

        // ---- S = Q K^T (Q pre-scaled) ----
        float accS[8][4] = {};
        #pragma unroll
        for (int s = 0; s < 16; s++) {
            uint32_t af[4];
            int qr = wid * 16 + l7 + ((grp & 1) << 3);
            int ch = s * 2 + (grp >> 1);
            ldm_x4(af, sq + qr * 512 + ((ch ^ (qr & 7)) << 4));
            #pragma unroll
            for (int np = 0; np < 4; np++) {
                uint32_t bf[4];
                int kr = np * 16 + l7 + ((grp >> 1) << 3);
                int c2 = s * 2 + (grp & 1);
                ldm_x4(bf, kb + kr * 512 + ((c2 ^ (kr & 7)) << 4));
                mma_f16(accS[np * 2],     af, &bf[0]);
                mma_f16(accS[np * 2 + 1], af, &bf[2]);
            }
        }

        if (k0 + 63 > q0 + wid * 16) {       // causal mask (diagonal tiles)
            #pragma unroll
            for (int nt = 0; nt < 8; nt++) {
                int c0 = k0 + nt * 8 + t2;
                if (c0 > qrow0)         accS[nt][0] = MASKV;
                if (c0 + 1 > qrow0)     accS[nt][1] = MASKV;
                if (c0 > qrow0 + 8)     accS[nt][2] = MASKV;
                if (c0 + 1 > qrow0 + 8) accS[nt][3] = MASKV;
            }
        }

        // ---- online softmax (log2 domain) ----
        float mx0 = MASKV, mx1 = MASKV;
        #pragma unroll
        for (int nt = 0; nt < 8; nt++) {
            mx0 = fmaxf(mx0, fmaxf(accS[nt][0], accS[nt][1]));
            mx1 = fmaxf(mx1, fmaxf(accS[nt][2], accS[nt][3]));
        }
        mx0 = fmaxf(mx0, __shfl_xor_sync(0xffffffffu, mx0, 1));
        mx0 = fmaxf(mx0, __shfl_xor_sync(0xffffffffu, mx0, 2));
        mx1 = fmaxf(mx1, __shfl_xor_sync(0xffffffffu, mx1, 1));
        mx1 = fmaxf(mx1, __shfl_xor_sync(0xffffffffu, mx1, 2));

        float mn0 = fmaxf(m0, mx0), mn1 = fmaxf(m1, mx1);
        int need = __any_sync(0xffffffffu, (mn0 != m0) || (mn1 != m1));
        float a0 = exp2f(m0 - mn0), a1 = exp2f(m1 - mn1);
        m0 = mn0; m1 = mn1;
        float s0 = 0.f, s1 = 0.f;
        #pragma unroll
        for (int nt = 0; nt < 8; nt++) {
            accS[nt][0] = exp2f(accS[nt][0] - mn0); s0 += accS[nt][0];
            accS[nt][1] = exp2f(accS[nt][1] - mn0); s0 += accS[nt][1];
            accS[nt][2] = exp2f(accS[nt][2] - mn1); s1 += accS[nt][2];
            accS[nt][3] = exp2f(accS[nt][3] - mn1); s1 += accS[nt][3];
        }
        s0 += __shfl_xor_sync(0xffffffffu, s0, 1);
        s0 += __shfl_xor_sync(0xffffffffu, s0, 2);
        s1 += __shfl_xor_sync(0xffffffffu, s1, 1);
        s1 += __shfl_xor_sync(0xffffffffu, s1, 2);
        l0 = l0 * a0 + s0;
        l1 = l1 * a1 + s1;
        if (need) {   // exact skip: a == 1 when no row max changed
            #pragma unroll
            for (int nt = 0; nt < 32; nt++) {
                accO[nt][0] *= a0; accO[nt][1] *= a0;
                accO[nt][2] *= a1; accO[nt][3] *= a1;
            }
        }

        // ---- P fragments (S accum layout == A operand layout) ----
        uint32_t pf[4][4];
        #pragma unroll
        for (int kc = 0; kc < 4; kc++) {
            pf[kc][0] = h2u(__floats2half2_rn(accS[2 * kc][0],     accS[2 * kc][1]));
            pf[kc][1] = h2u(__floats2half2_rn(accS[2 * kc][2],     accS[2 * kc][3]));
            pf[kc][2] = h2u(__floats2half2_rn(accS[2 * kc + 1][0], accS[2 * kc + 1][1]));
            pf[kc][3] = h2u(__floats2half2_rn(accS[2 * kc + 1][2], accS[2 * kc + 1][3]));
        }

        // ---- O += P V (kc outer) ----
        #pragma unroll
        for (int kc = 0; kc < 4; kc++) {
            #pragma unroll
            for (int np = 0; np < 16; np++) {
                uint32_t bf[4];
                int dr = np * 16 + l7 + ((grp >> 1) << 3);
                int ch = kc * 2 + (grp & 1);
                ldm_x4(bf, vb + dr * 128 + ((ch ^ (dr & 7)) << 4));
                mma_f16(accO[np * 2],     pf[kc], &bf[0]);
                mma_f16(accO[np * 2 + 1], pf[kc], &bf[2]);
            }
        }

        __syncthreads();
        if (it + 2 < niter) { fillKV(it + 2, it & 1); CP_COMMIT(); }
    }

    // ---- epilogue: 1/l, sigmoid gate, fp16 store ----
    float r0 = 1.f / l0, r1 = 1.f / l1;
    int trow0 = qrow0, trow1 = qrow0 + 8;
    const __half* G0 = Qh + (size_t)trow0 * QROW + h * 512 + 256;
    const __half* G1 = Qh + (size_t)trow1 * QROW + h * 512 + 256;
    __half* O0 = O + (size_t)trow0 * ODIM + h * 256;
    __half* O1 = O + (size_t)trow1 * ODIM + h * 256;
    #pragma unroll
    for (int nt = 0; nt < 32; nt++) {
        int d = nt * 8 + t2;
        float2 ga = __half22float2(*(const __half2*)(G0 + d));
        float2 gb = __half22float2(*(const __half2*)(G1 + d));
        float vx = accO[nt][0] * r0 / (1.f + __expf(-ga.x));
        float vy = accO[nt][1] * r0 / (1.f + __expf(-ga.y));
        float wx = accO[nt][2] * r1 / (1.f + __expf(-gb.x));
        float wy = accO[nt][3] * r1 / (1.f + __expf(-gb.y));
        *(__half2*)(O0 + d) = __floats2half2_rn(vx, vy);
        *(__half2*)(O1 + d) = __floats2half2_rn(wx, wy);
    }
}

// ============================ elementwise kernels ==========================
static constexpr long long F2H_N0 = (long long)SEQ * HIDDEN;
static constexpr long long F2H_N1 = (long long)QROW * HIDDEN;
static constexpr long long F2H_N2 = (long long)KROW * HIDDEN;
static constexpr long long F2H_N3 = (long long)KROW * HIDDEN;
static constexpr long long F2H_N4 = (long long)HIDDEN * ODIM;
static constexpr long long F2H_TOT = F2H_N0 + F2H_N1 + F2H_N2 + F2H_N3 + F2H_N4;

// 8 elements per thread: 2x LDG.128 -> 1x STG.128.
__global__ __launch_bounds__(256) void f2h_all(
    const float* __restrict__ s0, __half* __restrict__ d0,
    const float* __restrict__ s1, __half* __restrict__ d1,
    const float* __restrict__ s2, __half* __restrict__ d2,
    const float* __restrict__ s3, __half* __restrict__ d3,
    const float* __restrict__ s4, __half* __restrict__ d4)
{
    long long i = ((long long)blockIdx.x * 256 + threadIdx.x) * 8;
    if (i >= F2H_TOT) return;
    const float* s;
    __half* d;
    if (i < F2H_N0)                    { s = s0; d = d0; }
    else if ((i -= F2H_N0) < F2H_N1)   { s = s1; d = d1; }
    else if ((i -= F2H_N1) < F2H_N2)   { s = s2; d = d2; }
    else if ((i -= F2H_N2) < F2H_N3)   { s = s3; d = d3; }
    else { i -= F2H_N3;                  s = s4; d = d4; }
    float4 v0 = *reinterpret_cast<const float4*>(s + i);
    float4 v1 = *reinterpret_cast<const float4*>(s + i + 4);
    __half2 hv[4] = { __floats2half2_rn(v0.x, v0.y), __floats2half2_rn(v0.z, v0.w),
                      __floats2half2_rn(v1.x, v1.y), __floats2half2_rn(v1.z, v1.w) };
    *reinterpret_cast<uint4*>(d + i) = *reinterpret_cast<uint4*>(hv);
}

// RoPE cos/sin table: 2048 tokens x 32 freqs, one sincos per entry (vs 16x
// duplicated per-head inside rmsnorm). Reads positions -> fully general.
__global__ __launch_bounds__(256) void rope_table(
    const int* __restrict__ pos, float* __restrict__ ct, float* __restrict__ st)
{
    int i = blockIdx.x * 256 + threadIdx.x;     // SEQ*32 total
    int t = i >> 5, fi = i & 31;
    float inv = expf(-(float)fi * (16.118095650958322f / 32.0f));
    float sn, cs;
    sincosf((float)pos[t] * inv, &sn, &cs);
    ct[i] = cs;
    st[i] = sn;
}

// Warp-per-row RMSNorm + RoPE; q rows pre-scaled by ATTN_SCALE*log2(e).
// RoPE angles come from the precomputed table (hot in L2) -> no sincos here.
__global__ __launch_bounds__(256) void rmsnorm_rope_h(
    __half* __restrict__ xq, const float* __restrict__ wq,
    __half* __restrict__ xk, const float* __restrict__ wk,
    const float* __restrict__ ropec, const float* __restrict__ ropes)
{
    int widx = threadIdx.x >> 5, lane = threadIdx.x & 31;
    int ridx = blockIdx.x * 8 + widx;
    __half* row;
    const float* w;
    int t;
    float sc;
    if (ridx < SEQ * NHEAD) {
        t = ridx >> 4;
        int h = ridx & 15;
        row = xq + (size_t)t * QROW + (size_t)h * 512;
        w = wq;
        sc = ATTN_SCALE_L2E;
    } else {
        int r2 = ridx - SEQ * NHEAD;
        t = r2 >> 1;
        int h = r2 & 1;
        row = xk + (size_t)t * KROW + (size_t)h * HD;
        w = wk;
        sc = 1.0f;
    }

    uint4 raw = *reinterpret_cast<const uint4*>(row + lane * 8);
    __half2 hv[4];
    *reinterpret_cast<uint4*>(hv) = raw;
    float v[8];
    #pragma unroll
    for (int j = 0; j < 4; j++) {
        float2 f = __half22float2(hv[j]);
        v[2 * j] = f.x; v[2 * j + 1] = f.y;
    }
    float s = 0.f;
    #pragma unroll
    for (int j = 0; j < 8; j++) s += v[j] * v[j];
    #pragma unroll
    for (int o = 16; o; o >>= 1) s += __shfl_xor_sync(0xffffffffu, s, o);
    float rinv = rsqrtf(s * (1.0f / 256.0f) + 1e-6f) * sc;

    float4 w1 = *reinterpret_cast<const float4*>(w + lane * 8);
    float4 w2 = *reinterpret_cast<const float4*>(w + lane * 8 + 4);
    float y[8] = { v[0] * rinv * (1.0f + w1.x), v[1] * rinv * (1.0f + w1.y),
                   v[2] * rinv * (1.0f + w1.z), v[3] * rinv * (1.0f + w1.w),
                   v[4] * rinv * (1.0f + w2.x), v[5] * rinv * (1.0f + w2.y),
                   v[6] * rinv * (1.0f + w2.z), v[7] * rinv * (1.0f + w2.w) };

    // RoPE: dims 0..63 live in lanes 0..7; pair (d, d+32) is 4 lanes apart.
    float oth[8];
    #pragma unroll
    for (int j = 0; j < 8; j++) oth[j] = __shfl_xor_sync(0xffffffffu, y[j], 4);
    if (lane < 8) {
        int l4 = lane & 3;                       // freq block: fi = l4*8 + j
        const float* cb = ropec + (size_t)t * 32 + l4 * 8;
        const float* sb = ropes + (size_t)t * 32 + l4 * 8;
        float4 c0 = *reinterpret_cast<const float4*>(cb);
        float4 c1 = *reinterpret_cast<const float4*>(cb + 4);
        float4 s0 = *reinterpret_cast<const float4*>(sb);
        float4 s1 = *reinterpret_cast<const float4*>(sb + 4);
        float cs[8] = { c0.x, c0.y, c0.z, c0.w, c1.x, c1.y, c1.z, c1.w };
        float sn[8] = { s0.x, s0.y, s0.z, s0.w, s1.x, s1.y, s1.z, s1.w };
        #pragma unroll
        for (int j = 0; j < 8; j++) {
            if (lane < 4) y[j] = y[j] * cs[j] - oth[j] * sn[j];
            else          y[j] = y[j] * cs[j] + oth[j] * sn[j];
        }
    }
    #pragma unroll
    for (int j = 0; j < 4; j++) hv[j] = __floats2half2_rn(y[2 * j], y[2 * j + 1]);
    *reinterpret_cast<uint4*>(row + lane * 8) = *reinterpret_cast<uint4*>(hv);
}

// ============================ host launch ==================================
extern "C" void kernel_launch(void* const* d_in, const int* in_sizes, int n_in,
                              void* d_out, int out_size)
{
    const int*   positions = (const int*)d_in[0];
    const float* hs  = (const float*)d_in[1];
    const float* wq  = (const float*)d_in[2];
    const float* wk  = (const float*)d_in[3];
    const float* wv  = (const float*)d_in[4];
    const float* wo  = (const float*)d_in[5];
    const float* qnw = (const float*)d_in[6];
    const float* knw = (const float*)d_in[7];
    float* out = (float*)d_out;

    __half *hhs, *hwq, *hwk, *hwv, *hwo, *hq, *hk, *hvt, *ho;
    float *rc, *rs;
    cudaGetSymbolAddress((void**)&hhs, g_hs_h);
    cudaGetSymbolAddress((void**)&hwq, g_wq_h);
    cudaGetSymbolAddress((void**)&hwk, g_wk_h);
    cudaGetSymbolAddress((void**)&hwv, g_wv_h);
    cudaGetSymbolAddress((void**)&hwo, g_wo_h);
    cudaGetSymbolAddress((void**)&hq,  g_qout_h);
    cudaGetSymbolAddress((void**)&hk,  g_kbuf_h);
    cudaGetSymbolAddress((void**)&hvt, g_vt_h);
    cudaGetSymbolAddress((void**)&ho,  g_obuf_h);
    cudaGetSymbolAddress((void**)&rc,  g_ropec);
    cudaGetSymbolAddress((void**)&rs,  g_ropes);

    cudaFuncSetAttribute(hgemm_nt<false>,
                         cudaFuncAttributeMaxDynamicSharedMemorySize, SMEM_BYTES);
    cudaFuncSetAttribute(hgemm_qkv,
                         cudaFuncAttributeMaxDynamicSharedMemorySize, SMEM_BYTES);
    cudaFuncSetAttribute(flash_attn,
                         cudaFuncAttributeMaxDynamicSharedMemorySize, FSMEM);

    dim3 blk(256);

    // 0a) RoPE table (65K sincos, shared across all heads)
    rope_table<<<SEQ * 32 / 256, 256>>>(positions, rc, rs);
    // 0b) fp32 -> fp16 (single launch, all five buffers, 8 elems/thread)
    f2h_all<<<(int)((F2H_TOT / 8 + 255) / 256), 256>>>(
        hs, hhs, wq, hwq, wk, hwk, wv, hwv, wo, hwo);

    // 1) Q + K + V^T projections (one launch, 1152 CTAs, 128x128 tiles)
    hgemm_qkv<<<1152, blk, SMEM_BYTES>>>(hhs, hwq, hwk, hwv, hq, hk, hvt);

    // 2) RMSNorm + RoPE (table-based; q rows pre-scaled, k rows plain)
    rmsnorm_rope_h<<<(SEQ * NHEAD + SEQ * NKV) / 8, 256>>>(
        hq, qnw, hk, knw, rc, rs);

    // 3) Fused flash attention (scores + softmax + PV + gate)
    flash_attn<<<256, blk, FSMEM>>>(hq, hk, hvt, ho);

    // 4) Output projection (f32 out): out = ho @ wo^T
    hgemm_nt<false><<<dim3(HIDDEN / 128, SEQ / 128, 1), blk, SMEM_BYTES>>>(
        ho, hwo, out, ODIM, ODIM, ODIM, HIDDEN);
}